// round 1
// baseline (speedup 1.0000x reference)
#include <cuda_runtime.h>
#include <math.h>

#define B_    256
#define M_    196
#define E_    1024
#define H_    8
#define DH_   128
#define MID_  64
#define NBIG  (B_ * M_)   // 50176

// ---------------- scratch (device globals: no allocation in kernel_launch) ----
__device__ float g_scratch[(size_t)NBIG * E_];   // GEMM output pre-norm (reused)
__device__ float g_kt    [(size_t)NBIG * E_];    // k transposed  [B,H,M,Dh]
__device__ float g_v2t   [(size_t)NBIG * E_];    // v2 transposed [B,H,M,Dh]
__device__ float g_small [(size_t)B_ * E_];      // small GEMM scratch
__device__ float g_qt    [(size_t)B_ * E_];      // q  [B,H,Dh]
__device__ float g_v1t   [(size_t)B_ * E_];      // v1 [B,H,Dh]

// ---------------- GEMM: C[r,c] = sum_k A[r,k]*W[k,c] + bias[c] ----------------
// 128x128 tile, BK=16, 256 threads, 8x8 micro-tile. K = N = 1024 fixed.
__global__ __launch_bounds__(256) void gemm_bias_kernel(
    const float* __restrict__ A, const float* __restrict__ W,
    const float* __restrict__ bias, float* __restrict__ C)
{
    __shared__ __align__(16) float As[16][128];
    __shared__ __align__(16) float Bs[16][128];
    const int t    = threadIdx.x;
    const int brow = blockIdx.x * 128;
    const int bcol = blockIdx.y * 128;
    const int ty   = t >> 4;
    const int tx   = t & 15;

    float acc[8][8];
    #pragma unroll
    for (int i = 0; i < 8; ++i)
        #pragma unroll
        for (int j = 0; j < 8; ++j) acc[i][j] = 0.f;

    const float* Abase = A + (size_t)brow * E_;

    for (int k0 = 0; k0 < E_; k0 += 16) {
        #pragma unroll
        for (int l = 0; l < 2; ++l) {
            int i  = t + l * 256;
            int ar = i >> 2;
            int kc = (i & 3) << 2;
            float4 v = *(const float4*)(Abase + (size_t)ar * E_ + k0 + kc);
            As[kc + 0][ar] = v.x; As[kc + 1][ar] = v.y;
            As[kc + 2][ar] = v.z; As[kc + 3][ar] = v.w;
        }
        #pragma unroll
        for (int l = 0; l < 2; ++l) {
            int i  = t + l * 256;
            int kr = i >> 5;
            int c  = (i & 31) << 2;
            *(float4*)&Bs[kr][c] = *(const float4*)(W + (size_t)(k0 + kr) * E_ + bcol + c);
        }
        __syncthreads();
        #pragma unroll
        for (int kk = 0; kk < 16; ++kk) {
            float a[8], b[8];
            *(float4*)&a[0] = *(const float4*)&As[kk][ty * 8];
            *(float4*)&a[4] = *(const float4*)&As[kk][ty * 8 + 4];
            *(float4*)&b[0] = *(const float4*)&Bs[kk][tx * 8];
            *(float4*)&b[4] = *(const float4*)&Bs[kk][tx * 8 + 4];
            #pragma unroll
            for (int i = 0; i < 8; ++i)
                #pragma unroll
                for (int j = 0; j < 8; ++j)
                    acc[i][j] = fmaf(a[i], b[j], acc[i][j]);
        }
        __syncthreads();
    }

    float bv[8];
    #pragma unroll
    for (int j = 0; j < 8; ++j) bv[j] = bias[bcol + tx * 8 + j];
    #pragma unroll
    for (int i = 0; i < 8; ++i) {
        size_t roff = (size_t)(brow + ty * 8 + i) * E_ + bcol + tx * 8;
        float4 o0 = make_float4(acc[i][0] + bv[0], acc[i][1] + bv[1],
                                acc[i][2] + bv[2], acc[i][3] + bv[3]);
        float4 o1 = make_float4(acc[i][4] + bv[4], acc[i][5] + bv[5],
                                acc[i][6] + bv[6], acc[i][7] + bv[7]);
        *(float4*)(C + roff)     = o0;
        *(float4*)(C + roff + 4) = o1;
    }
}

// ------------- CELU(alpha=1.3) + GroupNorm(8 groups) + layout transpose -------
// grid = (rows, 8 groups), 128 threads (one per channel in group).
// out[((b*H + g)*Mparam + m)*128 + d] — for q/v1 pass Mparam=1.
__global__ __launch_bounds__(128) void celu_gnorm_kernel(
    const float* __restrict__ Y, const float* __restrict__ gw,
    const float* __restrict__ gb, float* __restrict__ out, int Mparam)
{
    const int row = blockIdx.x;
    const int g   = blockIdx.y;
    const int d   = threadIdx.x;

    float x = Y[(size_t)row * E_ + g * DH_ + d];
    x = (x > 0.f) ? x : 1.3f * expm1f(x * (1.0f / 1.3f));

    float s = x, s2 = x * x;
    #pragma unroll
    for (int o = 16; o; o >>= 1) {
        s  += __shfl_xor_sync(0xffffffffu, s,  o);
        s2 += __shfl_xor_sync(0xffffffffu, s2, o);
    }
    __shared__ float rs[4], rs2[4];
    if ((d & 31) == 0) { rs[d >> 5] = s; rs2[d >> 5] = s2; }
    __syncthreads();
    s  = rs[0]  + rs[1]  + rs[2]  + rs[3];
    s2 = rs2[0] + rs2[1] + rs2[2] + rs2[3];

    const float inv = 1.0f / 128.0f;
    float mean = s * inv;
    float var  = s2 * inv - mean * mean;
    float xn   = (x - mean) * rsqrtf(var + 1e-5f);
    float o    = fmaf(xn, gw[g * DH_ + d], gb[g * DH_ + d]);

    int b = row / Mparam;
    int m = row - b * Mparam;
    out[(((size_t)b * H_ + g) * Mparam + m) * DH_ + d] = o;
}

// ---------------- fused back half: one block per (b,h) -----------------------
// hidden = relu((q*k) @ Wb + bb); masked mean-pool; masked softmax over
// hidden@Ws; v2 pooling; sigmoid(pool@Wc + bc); out = v1 * v2p * gate.
__global__ __launch_bounds__(256) void attn_kernel(
    const float* __restrict__ qt,  const float* __restrict__ v1t,
    const float* __restrict__ kt,  const float* __restrict__ v2t,
    const int*   __restrict__ mask,
    const float* __restrict__ Wb,  const float* __restrict__ bb,
    const float* __restrict__ Ws,  const float* __restrict__ bs,
    const float* __restrict__ Wc,  const float* __restrict__ bc,
    float* __restrict__ out)
{
    const int bh  = blockIdx.x;          // b*H + h
    const int b   = bh >> 3;
    const int t   = threadIdx.x;
    const int sub = t >> 6;              // 4 subgroups, one m each
    const int mid = t & 63;              // MID channel

    __shared__ __align__(16) float Wb_s[DH_ * MID_];   // 32 KB
    __shared__ __align__(16) float q_s[DH_];
    __shared__ __align__(16) float a_s[4][DH_];
    __shared__ float mk_s[M_];
    __shared__ float s_s[M_];
    __shared__ float Ws_s[MID_];
    __shared__ float red_s[8];
    __shared__ float red2[8];
    __shared__ float pool4[4][MID_];
    __shared__ float pool_s[MID_];
    __shared__ float vp_s[256];
    __shared__ float sc_s[1];            // summask

    for (int i = t; i < DH_ * MID_; i += 256) Wb_s[i] = Wb[i];
    if (t < DH_)  q_s[t]  = qt[(size_t)bh * DH_ + t];
    if (t < MID_) Ws_s[t] = Ws[t];

    float mv = 0.f;
    if (t < M_) { mv = (float)mask[b * M_ + t]; mk_s[t] = mv; }
    float r = mv;
    #pragma unroll
    for (int o = 16; o; o >>= 1) r += __shfl_xor_sync(0xffffffffu, r, o);
    if ((t & 31) == 0) red2[t >> 5] = r;
    __syncthreads();
    if (t == 0) {
        float smk = 0.f;
        #pragma unroll
        for (int i = 0; i < 8; ++i) smk += red2[i];
        sc_s[0] = smk;
    }
    __syncthreads();

    const float bsv = bs[0];
    const float bbv = bb[mid];
    const float wsv = Ws_s[mid];
    const float* kbase  = kt  + (size_t)bh * M_ * DH_;
    const float* v2base = v2t + (size_t)bh * M_ * DH_;
    float pool_reg = 0.f;

    for (int m0 = 0; m0 < M_; m0 += 4) {            // 196 divisible by 4
        const int m = m0 + sub;
        const float* krow = kbase + (size_t)m * DH_;
        a_s[sub][mid]      = q_s[mid]      * krow[mid];
        a_s[sub][mid + 64] = q_s[mid + 64] * krow[mid + 64];
        __syncthreads();

        const float* asub = a_s[sub];
        float h = bbv;
        #pragma unroll
        for (int d4 = 0; d4 < 32; ++d4) {
            float4 a4 = *(const float4*)(asub + (d4 << 2));
            h = fmaf(a4.x, Wb_s[((d4 << 2) + 0) * MID_ + mid], h);
            h = fmaf(a4.y, Wb_s[((d4 << 2) + 1) * MID_ + mid], h);
            h = fmaf(a4.z, Wb_s[((d4 << 2) + 2) * MID_ + mid], h);
            h = fmaf(a4.w, Wb_s[((d4 << 2) + 3) * MID_ + mid], h);
        }
        h = fmaxf(h, 0.f);
        pool_reg += h * mk_s[m];

        float sv = h * wsv;
        #pragma unroll
        for (int o = 16; o; o >>= 1) sv += __shfl_xor_sync(0xffffffffu, sv, o);
        if ((t & 31) == 0) red_s[t >> 5] = sv;
        __syncthreads();
        if (mid == 0) {
            float tot = red_s[sub * 2] + red_s[sub * 2 + 1] + bsv;
            s_s[m] = (mk_s[m] != 0.f) ? tot : -1e9f;
        }
        // next iter's a_s/red_s writes are after its own __syncthreads()
    }
    pool4[sub][mid] = pool_reg;
    __syncthreads();
    if (t < MID_) {
        float p = pool4[0][t] + pool4[1][t] + pool4[2][t] + pool4[3][t];
        pool_s[t] = p / sc_s[0];
    }

    // ---- masked softmax over s_s[0..195] ----
    float xv = (t < M_) ? s_s[t] : -3.4e38f;
    float mx = xv;
    #pragma unroll
    for (int o = 16; o; o >>= 1) mx = fmaxf(mx, __shfl_xor_sync(0xffffffffu, mx, o));
    if ((t & 31) == 0) red2[t >> 5] = mx;
    __syncthreads();
    mx = red2[0];
    #pragma unroll
    for (int i = 1; i < 8; ++i) mx = fmaxf(mx, red2[i]);
    float e  = (t < M_) ? expf(xv - mx) : 0.f;
    float zs = e;
    #pragma unroll
    for (int o = 16; o; o >>= 1) zs += __shfl_xor_sync(0xffffffffu, zs, o);
    __syncthreads();
    if ((t & 31) == 0) red2[t >> 5] = zs;
    __syncthreads();
    float Z = red2[0] + red2[1] + red2[2] + red2[3] +
              red2[4] + red2[5] + red2[6] + red2[7];
    if (t < M_) s_s[t] = e / Z;
    __syncthreads();

    // ---- v2_pooled[d] = sum_m p[m] * v2[b,h,m,d] ----
    {
        int d = t & 127, half = t >> 7;
        float acc2 = 0.f;
        for (int m = half; m < M_; m += 2)
            acc2 += s_s[m] * v2base[(size_t)m * DH_ + d];
        vp_s[t] = acc2;
    }
    __syncthreads();

    if (t < DH_) {
        float v2p = vp_s[t] + vp_s[t + 128];
        float ac = bc[t];
        #pragma unroll
        for (int midi = 0; midi < MID_; ++midi)
            ac = fmaf(pool_s[midi], Wc[midi * DH_ + t], ac);
        ac = 1.0f / (1.0f + expf(-ac));
        out[(size_t)bh * DH_ + t] = v1t[(size_t)bh * DH_ + t] * v2p * ac;
    }
}

// ------------------------------- launcher ------------------------------------
extern "C" void kernel_launch(void* const* d_in, const int* in_sizes, int n_in,
                              void* d_out, int out_size)
{
    (void)in_sizes; (void)n_in; (void)out_size;
    const float* query  = (const float*)d_in[0];
    const float* key    = (const float*)d_in[1];
    const int*   mask   = (const int*)  d_in[2];
    const float* value1 = (const float*)d_in[3];
    const float* value2 = (const float*)d_in[4];
    const float* Wq   = (const float*)d_in[5];
    const float* bq   = (const float*)d_in[6];
    const float* gq_w = (const float*)d_in[7];
    const float* gq_b = (const float*)d_in[8];
    const float* Wk   = (const float*)d_in[9];
    const float* bk   = (const float*)d_in[10];
    const float* gk_w = (const float*)d_in[11];
    const float* gk_b = (const float*)d_in[12];
    const float* Wv1  = (const float*)d_in[13];
    const float* bv1  = (const float*)d_in[14];
    const float* gv1_w= (const float*)d_in[15];
    const float* gv1_b= (const float*)d_in[16];
    const float* Wv2  = (const float*)d_in[17];
    const float* bv2  = (const float*)d_in[18];
    const float* gv2_w= (const float*)d_in[19];
    const float* gv2_b= (const float*)d_in[20];
    const float* Wb   = (const float*)d_in[21];
    const float* bb   = (const float*)d_in[22];
    const float* Ws   = (const float*)d_in[23];
    const float* bs   = (const float*)d_in[24];
    const float* Wc   = (const float*)d_in[25];
    const float* bc   = (const float*)d_in[26];

    float *scr, *ktp, *v2tp, *smallp, *qtp, *v1tp;
    cudaGetSymbolAddress((void**)&scr,    g_scratch);
    cudaGetSymbolAddress((void**)&ktp,    g_kt);
    cudaGetSymbolAddress((void**)&v2tp,   g_v2t);
    cudaGetSymbolAddress((void**)&smallp, g_small);
    cudaGetSymbolAddress((void**)&qtp,    g_qt);
    cudaGetSymbolAddress((void**)&v1tp,   g_v1t);

    dim3 gBig(NBIG / 128, E_ / 128);    // (392, 8)
    dim3 gSmall(B_ / 128, E_ / 128);    // (2, 8)

    // k projection
    gemm_bias_kernel<<<gBig, 256>>>(key, Wk, bk, scr);
    celu_gnorm_kernel<<<dim3(NBIG, H_), 128>>>(scr, gk_w, gk_b, ktp, M_);
    // v2 projection
    gemm_bias_kernel<<<gBig, 256>>>(value2, Wv2, bv2, scr);
    celu_gnorm_kernel<<<dim3(NBIG, H_), 128>>>(scr, gv2_w, gv2_b, v2tp, M_);
    // q projection
    gemm_bias_kernel<<<gSmall, 256>>>(query, Wq, bq, smallp);
    celu_gnorm_kernel<<<dim3(B_, H_), 128>>>(smallp, gq_w, gq_b, qtp, 1);
    // v1 projection
    gemm_bias_kernel<<<gSmall, 256>>>(value1, Wv1, bv1, smallp);
    celu_gnorm_kernel<<<dim3(B_, H_), 128>>>(smallp, gv1_w, gv1_b, v1tp, 1);
    // fused attention back-half
    attn_kernel<<<B_ * H_, 256>>>(qtp, v1tp, ktp, v2tp, mask,
                                  Wb, bb, Ws, bs, Wc, bc, (float*)d_out);
}

// round 2
// speedup vs baseline: 1.4579x; 1.4579x over previous
#include <cuda_runtime.h>
#include <cuda_bf16.h>
#include <math.h>

#define B_    256
#define M_    196
#define E_    1024
#define H_    8
#define DH_   128
#define MID_  64
#define NBIG  (B_ * M_)   // 50176

// ---------------- persistent scratch (no allocations allowed) -----------------
__device__ float g_kt [(size_t)NBIG * E_];   // k  [B,H,M,Dh]
__device__ float g_v2t[(size_t)NBIG * E_];   // v2 [B,H,M,Dh]
__device__ float g_qt [(size_t)B_ * E_];     // q  [B,H,Dh]
__device__ float g_v1t[(size_t)B_ * E_];     // v1 [B,H,Dh]

// ---------------- smem layout constants (in 32-bit words) ---------------------
// per buffer: Ahi[2112] Alo[2112] Bhi[2112] Blo[2112]  (ABLK=33 padded blocks)
#define ABLK      33
#define A_WORDS   2112      // 16 blocks * 33 * 4
#define B_WORDS   2112      // 32 blocks * 33 * 2
#define BUF_WORDS 8448
#define SMEM_BYTES (2 * BUF_WORDS * 4)   // 67584

__device__ __forceinline__ void split2(float f0, float f1,
                                       unsigned &hi, unsigned &lo)
{
    __nv_bfloat16 h0 = __float2bfloat16(f0);
    __nv_bfloat16 h1 = __float2bfloat16(f1);
    float r0 = f0 - __bfloat162float(h0);
    float r1 = f1 - __bfloat162float(h1);
    __nv_bfloat16 l0 = __float2bfloat16(r0);
    __nv_bfloat16 l1 = __float2bfloat16(r1);
    hi = (unsigned)__bfloat16_as_ushort(h0) |
         ((unsigned)__bfloat16_as_ushort(h1) << 16);
    lo = (unsigned)__bfloat16_as_ushort(l0) |
         ((unsigned)__bfloat16_as_ushort(l1) << 16);
}

__device__ __forceinline__ void mma16816(float* c, uint4 a, uint2 b)
{
    asm volatile(
        "mma.sync.aligned.m16n8k16.row.col.f32.bf16.bf16.f32 "
        "{%0,%1,%2,%3}, {%4,%5,%6,%7}, {%8,%9}, {%0,%1,%2,%3};\n"
        : "+f"(c[0]), "+f"(c[1]), "+f"(c[2]), "+f"(c[3])
        : "r"(a.x), "r"(a.y), "r"(a.z), "r"(a.w), "r"(b.x), "r"(b.y));
}

// =============================================================================
// GEMM (rows x 1024) @ (1024 x 1024) + bias, then CELU + GroupNorm over the
// 128-col tile (== one group) + transposed store out[((b*H+g)*Mp + m)*128 + c].
// Block tile 128x128, BK=32, 8 warps (2x4), warp tile 64x32, bf16x3 mma.
// =============================================================================
__global__ __launch_bounds__(256) void gemm_fused(
    const float* __restrict__ A, const float* __restrict__ W,
    const float* __restrict__ bias, const float* __restrict__ gw,
    const float* __restrict__ gb, float* __restrict__ out, int Mp)
{
    extern __shared__ unsigned sm[];
    const int t    = threadIdx.x;
    const int lane = t & 31;
    const int warp = t >> 5;
    const int wm   = warp >> 2;      // 0..1
    const int wn   = warp & 3;       // 0..3
    const int brow = blockIdx.x * 128;
    const int gidx = blockIdx.y;     // group / column block
    const int bcol = gidx * DH_;

    // ---- producer (A): thread -> row pr, k-half pkh ----
    const int pr   = t >> 1;            // 0..127
    const int pkh  = (t & 1) << 4;      // 0 / 16
    const int pks  = t & 1;             // k16 step
    const int pmg  = pr >> 4;           // m-tile 0..7
    const int plr  = pr & 15;
    const int ablk0 = (pmg * 2 + pks) * ABLK;
    const int preg0 = (plr >> 3) & 1;
    const int plf   = (plr & 7) << 2;

    // ---- producer (B): thread -> n-group bng, k-pair bkp ----
    const int bng  = t >> 4;            // 0..15
    const int bkp  = t & 15;            // 0..15
    const int bks  = bkp >> 3;
    const int breg = (bkp >> 2) & 1;
    const int btig = bkp & 3;
    const int bblk0 = (bng * 2 + bks) * ABLK;

    const float* Aptr = A + (size_t)(brow + pr) * E_ + pkh;
    const float* Wptr = W + (size_t)(2 * bkp) * E_ + bcol + bng * 8;

    float av[16], wv[16];
    #pragma unroll
    for (int i = 0; i < 4; ++i)
        *(float4*)&av[i * 4] = *(const float4*)(Aptr + i * 4);
    #pragma unroll
    for (int i = 0; i < 2; ++i)
        *(float4*)&wv[i * 4] = *(const float4*)(Wptr + i * 4);
    #pragma unroll
    for (int i = 0; i < 2; ++i)
        *(float4*)&wv[8 + i * 4] = *(const float4*)(Wptr + E_ + i * 4);

    float acc[4][4][4];
    #pragma unroll
    for (int mt = 0; mt < 4; ++mt)
        #pragma unroll
        for (int nt = 0; nt < 4; ++nt)
            #pragma unroll
            for (int c = 0; c < 4; ++c) acc[mt][nt][c] = 0.f;

    auto store_tile = [&](int buf) {
        unsigned* Ahi = sm + buf * BUF_WORDS;
        unsigned* Alo = Ahi + A_WORDS;
        unsigned* Bhi = Ahi + 2 * A_WORDS;
        unsigned* Blo = Ahi + 2 * A_WORDS + B_WORDS;
        #pragma unroll
        for (int p = 0; p < 8; ++p) {
            unsigned hi, lo;
            split2(av[2 * p], av[2 * p + 1], hi, lo);
            int lf  = plf | (p & 3);
            int reg = preg0 | ((p >> 2) << 1);
            int w   = (ablk0 + lf) * 4 + reg;
            Ahi[w] = hi;  Alo[w] = lo;
        }
        #pragma unroll
        for (int j = 0; j < 8; ++j) {
            unsigned hi, lo;
            split2(wv[j], wv[8 + j], hi, lo);     // low half = smaller k
            int lf = (j << 2) | btig;
            int w  = (bblk0 + lf) * 2 + breg;
            Bhi[w] = hi;  Blo[w] = lo;
        }
    };

    store_tile(0);
    __syncthreads();

    for (int kt = 0; kt < 32; ++kt) {
        const unsigned* Ahi = sm + (kt & 1) * BUF_WORDS;
        const unsigned* Alo = Ahi + A_WORDS;
        const unsigned* Bhi = Ahi + 2 * A_WORDS;
        const unsigned* Blo = Ahi + 2 * A_WORDS + B_WORDS;

        if (kt < 31) {
            const float* Ap = Aptr + (kt + 1) * 32;
            const float* Wp = Wptr + (size_t)(kt + 1) * 32 * E_;
            #pragma unroll
            for (int i = 0; i < 4; ++i)
                *(float4*)&av[i * 4] = *(const float4*)(Ap + i * 4);
            #pragma unroll
            for (int i = 0; i < 2; ++i)
                *(float4*)&wv[i * 4] = *(const float4*)(Wp + i * 4);
            #pragma unroll
            for (int i = 0; i < 2; ++i)
                *(float4*)&wv[8 + i * 4] = *(const float4*)(Wp + E_ + i * 4);
        }

        #pragma unroll
        for (int ks = 0; ks < 2; ++ks) {
            uint2 bh[4], bl[4];
            #pragma unroll
            for (int nt = 0; nt < 4; ++nt) {
                int blk = ((wn * 4 + nt) * 2 + ks) * ABLK + lane;
                bh[nt] = *(const uint2*)(Bhi + blk * 2);
                bl[nt] = *(const uint2*)(Blo + blk * 2);
            }
            #pragma unroll
            for (int mt = 0; mt < 4; ++mt) {
                int blk = ((wm * 4 + mt) * 2 + ks) * ABLK + lane;
                uint4 ah = *(const uint4*)(Ahi + blk * 4);
                uint4 al = *(const uint4*)(Alo + blk * 4);
                #pragma unroll
                for (int nt = 0; nt < 4; ++nt) {
                    mma16816(acc[mt][nt], ah, bh[nt]);
                    mma16816(acc[mt][nt], ah, bl[nt]);
                    mma16816(acc[mt][nt], al, bh[nt]);
                }
            }
        }

        if (kt < 31) store_tile((kt + 1) & 1);
        __syncthreads();
    }

    // ---------------- epilogue: bias + CELU -> stage -> GroupNorm -> out ------
    float* stage = (float*)sm;          // [128][130]
    const int g   = lane >> 2;
    const int tig = lane & 3;

    #pragma unroll
    for (int mt = 0; mt < 4; ++mt) {
        int row = wm * 64 + mt * 16 + g;
        #pragma unroll
        for (int nt = 0; nt < 4; ++nt) {
            int col = wn * 32 + nt * 8 + tig * 2;
            float2 bv = *(const float2*)(bias + bcol + col);
            float x0 = acc[mt][nt][0] + bv.x;
            float x1 = acc[mt][nt][1] + bv.y;
            float x2 = acc[mt][nt][2] + bv.x;
            float x3 = acc[mt][nt][3] + bv.y;
            x0 = (x0 > 0.f) ? x0 : 1.3f * expm1f(x0 * (1.f / 1.3f));
            x1 = (x1 > 0.f) ? x1 : 1.3f * expm1f(x1 * (1.f / 1.3f));
            x2 = (x2 > 0.f) ? x2 : 1.3f * expm1f(x2 * (1.f / 1.3f));
            x3 = (x3 > 0.f) ? x3 : 1.3f * expm1f(x3 * (1.f / 1.3f));
            *(float2*)&stage[row * 130 + col]       = make_float2(x0, x1);
            *(float2*)&stage[(row + 8) * 130 + col] = make_float2(x2, x3);
        }
    }
    __syncthreads();

    // each warp normalizes 16 rows
    for (int rr = 0; rr < 16; ++rr) {
        int row = warp * 16 + rr;
        float x[4];
        #pragma unroll
        for (int i = 0; i < 4; ++i) x[i] = stage[row * 130 + lane + 32 * i];
        float s = 0.f, s2 = 0.f;
        #pragma unroll
        for (int i = 0; i < 4; ++i) { s += x[i]; s2 += x[i] * x[i]; }
        #pragma unroll
        for (int o = 16; o; o >>= 1) {
            s  += __shfl_xor_sync(0xffffffffu, s,  o);
            s2 += __shfl_xor_sync(0xffffffffu, s2, o);
        }
        float mean = s * (1.f / 128.f);
        float var  = s2 * (1.f / 128.f) - mean * mean;
        float rstd = rsqrtf(var + 1e-5f);
        int rg = brow + row;
        int b  = rg / Mp;
        int m  = rg - b * Mp;
        float* op = out + (((size_t)b * H_ + gidx) * Mp + m) * DH_;
        #pragma unroll
        for (int i = 0; i < 4; ++i) {
            int c = lane + 32 * i;
            op[c] = (x[i] - mean) * rstd * gw[bcol + c] + gb[bcol + c];
        }
    }
}

// ---------------- fused back half: one block per (b,h) -----------------------
__global__ __launch_bounds__(256) void attn_kernel(
    const float* __restrict__ qt,  const float* __restrict__ v1t,
    const float* __restrict__ kt,  const float* __restrict__ v2t,
    const int*   __restrict__ mask,
    const float* __restrict__ Wb,  const float* __restrict__ bb,
    const float* __restrict__ Ws,  const float* __restrict__ bs,
    const float* __restrict__ Wc,  const float* __restrict__ bc,
    float* __restrict__ out)
{
    const int bh  = blockIdx.x;
    const int b   = bh >> 3;
    const int t   = threadIdx.x;
    const int sub = t >> 6;
    const int mid = t & 63;

    __shared__ __align__(16) float Wb_s[DH_ * MID_];
    __shared__ __align__(16) float q_s[DH_];
    __shared__ __align__(16) float a_s[4][DH_];
    __shared__ float mk_s[M_];
    __shared__ float s_s[M_];
    __shared__ float Ws_s[MID_];
    __shared__ float red_s[8];
    __shared__ float red2[8];
    __shared__ float pool4[4][MID_];
    __shared__ float pool_s[MID_];
    __shared__ float vp_s[256];
    __shared__ float sc_s[1];

    for (int i = t; i < DH_ * MID_; i += 256) Wb_s[i] = Wb[i];
    if (t < DH_)  q_s[t]  = qt[(size_t)bh * DH_ + t];
    if (t < MID_) Ws_s[t] = Ws[t];

    float mv = 0.f;
    if (t < M_) { mv = (float)mask[b * M_ + t]; mk_s[t] = mv; }
    float r = mv;
    #pragma unroll
    for (int o = 16; o; o >>= 1) r += __shfl_xor_sync(0xffffffffu, r, o);
    if ((t & 31) == 0) red2[t >> 5] = r;
    __syncthreads();
    if (t == 0) {
        float smk = 0.f;
        #pragma unroll
        for (int i = 0; i < 8; ++i) smk += red2[i];
        sc_s[0] = smk;
    }
    __syncthreads();

    const float bsv = bs[0];
    const float bbv = bb[mid];
    const float wsv = Ws_s[mid];
    const float* kbase  = kt  + (size_t)bh * M_ * DH_;
    const float* v2base = v2t + (size_t)bh * M_ * DH_;
    float pool_reg = 0.f;

    for (int m0 = 0; m0 < M_; m0 += 4) {
        const int m = m0 + sub;
        const float* krow = kbase + (size_t)m * DH_;
        a_s[sub][mid]      = q_s[mid]      * krow[mid];
        a_s[sub][mid + 64] = q_s[mid + 64] * krow[mid + 64];
        __syncthreads();

        const float* asub = a_s[sub];
        float h = bbv;
        #pragma unroll
        for (int d4 = 0; d4 < 32; ++d4) {
            float4 a4 = *(const float4*)(asub + (d4 << 2));
            h = fmaf(a4.x, Wb_s[((d4 << 2) + 0) * MID_ + mid], h);
            h = fmaf(a4.y, Wb_s[((d4 << 2) + 1) * MID_ + mid], h);
            h = fmaf(a4.z, Wb_s[((d4 << 2) + 2) * MID_ + mid], h);
            h = fmaf(a4.w, Wb_s[((d4 << 2) + 3) * MID_ + mid], h);
        }
        h = fmaxf(h, 0.f);
        pool_reg += h * mk_s[m];

        float sv = h * wsv;
        #pragma unroll
        for (int o = 16; o; o >>= 1) sv += __shfl_xor_sync(0xffffffffu, sv, o);
        if ((t & 31) == 0) red_s[t >> 5] = sv;
        __syncthreads();
        if (mid == 0) {
            float tot = red_s[sub * 2] + red_s[sub * 2 + 1] + bsv;
            s_s[m] = (mk_s[m] != 0.f) ? tot : -1e9f;
        }
    }
    pool4[sub][mid] = pool_reg;
    __syncthreads();
    if (t < MID_) {
        float p = pool4[0][t] + pool4[1][t] + pool4[2][t] + pool4[3][t];
        pool_s[t] = p / sc_s[0];
    }

    float xv = (t < M_) ? s_s[t] : -3.4e38f;
    float mx = xv;
    #pragma unroll
    for (int o = 16; o; o >>= 1) mx = fmaxf(mx, __shfl_xor_sync(0xffffffffu, mx, o));
    if ((t & 31) == 0) red2[t >> 5] = mx;
    __syncthreads();
    mx = red2[0];
    #pragma unroll
    for (int i = 1; i < 8; ++i) mx = fmaxf(mx, red2[i]);
    float e  = (t < M_) ? expf(xv - mx) : 0.f;
    float zs = e;
    #pragma unroll
    for (int o = 16; o; o >>= 1) zs += __shfl_xor_sync(0xffffffffu, zs, o);
    __syncthreads();
    if ((t & 31) == 0) red2[t >> 5] = zs;
    __syncthreads();
    float Z = red2[0] + red2[1] + red2[2] + red2[3] +
              red2[4] + red2[5] + red2[6] + red2[7];
    if (t < M_) s_s[t] = e / Z;
    __syncthreads();

    {
        int d = t & 127, half = t >> 7;
        float acc2 = 0.f;
        for (int m = half; m < M_; m += 2)
            acc2 += s_s[m] * v2base[(size_t)m * DH_ + d];
        vp_s[t] = acc2;
    }
    __syncthreads();

    if (t < DH_) {
        float v2p = vp_s[t] + vp_s[t + 128];
        float ac = bc[t];
        #pragma unroll
        for (int midi = 0; midi < MID_; ++midi)
            ac = fmaf(pool_s[midi], Wc[midi * DH_ + t], ac);
        ac = 1.0f / (1.0f + expf(-ac));
        out[(size_t)bh * DH_ + t] = v1t[(size_t)bh * DH_ + t] * v2p * ac;
    }
}

// ------------------------------- launcher ------------------------------------
extern "C" void kernel_launch(void* const* d_in, const int* in_sizes, int n_in,
                              void* d_out, int out_size)
{
    (void)in_sizes; (void)n_in; (void)out_size;
    const float* query  = (const float*)d_in[0];
    const float* key    = (const float*)d_in[1];
    const int*   mask   = (const int*)  d_in[2];
    const float* value1 = (const float*)d_in[3];
    const float* value2 = (const float*)d_in[4];
    const float* Wq   = (const float*)d_in[5];
    const float* bq   = (const float*)d_in[6];
    const float* gq_w = (const float*)d_in[7];
    const float* gq_b = (const float*)d_in[8];
    const float* Wk   = (const float*)d_in[9];
    const float* bk   = (const float*)d_in[10];
    const float* gk_w = (const float*)d_in[11];
    const float* gk_b = (const float*)d_in[12];
    const float* Wv1  = (const float*)d_in[13];
    const float* bv1  = (const float*)d_in[14];
    const float* gv1_w= (const float*)d_in[15];
    const float* gv1_b= (const float*)d_in[16];
    const float* Wv2  = (const float*)d_in[17];
    const float* bv2  = (const float*)d_in[18];
    const float* gv2_w= (const float*)d_in[19];
    const float* gv2_b= (const float*)d_in[20];
    const float* Wb   = (const float*)d_in[21];
    const float* bb   = (const float*)d_in[22];
    const float* Ws   = (const float*)d_in[23];
    const float* bs   = (const float*)d_in[24];
    const float* Wc   = (const float*)d_in[25];
    const float* bc   = (const float*)d_in[26];

    float *ktp, *v2tp, *qtp, *v1tp;
    cudaGetSymbolAddress((void**)&ktp,  g_kt);
    cudaGetSymbolAddress((void**)&v2tp, g_v2t);
    cudaGetSymbolAddress((void**)&qtp,  g_qt);
    cudaGetSymbolAddress((void**)&v1tp, g_v1t);

    cudaFuncSetAttribute(gemm_fused,
                         cudaFuncAttributeMaxDynamicSharedMemorySize, SMEM_BYTES);

    dim3 gBig(NBIG / 128, 8);     // (392, 8)
    dim3 gSmall(B_ / 128, 8);     // (2, 8)

    gemm_fused<<<gBig,   256, SMEM_BYTES>>>(key,    Wk,  bk,  gk_w,  gk_b,  ktp,  M_);
    gemm_fused<<<gBig,   256, SMEM_BYTES>>>(value2, Wv2, bv2, gv2_w, gv2_b, v2tp, M_);
    gemm_fused<<<gSmall, 256, SMEM_BYTES>>>(query,  Wq,  bq,  gq_w,  gq_b,  qtp,  1);
    gemm_fused<<<gSmall, 256, SMEM_BYTES>>>(value1, Wv1, bv1, gv1_w, gv1_b, v1tp, 1);

    attn_kernel<<<B_ * H_, 256>>>(qtp, v1tp, ktp, v2tp, mask,
                                  Wb, bb, Ws, bs, Wc, bc, (float*)d_out);
}